// round 15
// baseline (speedup 1.0000x reference)
#include <cuda_runtime.h>
#include <cuda_fp16.h>
#include <cstdint>

#define TT 48
#define CC 64
#define H1 256
#define H2 128
#define NPRED 12
#define SEQS 32768
#define GRID_A 148
#define GRID_B 148
#define NTILE_B 256

#define PX 40
#define PW 104
#define PHC 66

// kernel A smem (bytes)
#define O_WF   0
#define O_G    13312
#define O_BEFF 21504
#define O_C0R  21760
#define O_C2R  22016
#define O_WB   22272
#define O_XB   23552
#define O_HC   89088
#define O_WS   191488
#define SMEMA  199680

// MLP smem
#define M_LAST 0
#define M_Z2   0
#define M_W1   18432
#define M_Z1   55296
#define M_W2   122880
#define M_W3   190464
#define SMEMB  194816

#define MMA(d,a0,a1,a2,a3,b0,b1) \
  asm volatile("mma.sync.aligned.m16n8k16.row.col.f32.f16.f16.f32 " \
  "{%0,%1,%2,%3}, {%4,%5,%6,%7}, {%8,%9}, {%0,%1,%2,%3};" \
  : "+f"((d)[0]),"+f"((d)[1]),"+f"((d)[2]),"+f"((d)[3]) \
  : "r"(a0),"r"(a1),"r"(a2),"r"(a3),"r"(b0),"r"(b1))

__device__ float g_last[SEQS * CC];
__device__ unsigned short g_W1p[H1 * 72];
__device__ float g_b1p[H1];

__device__ __forceinline__ uint16_t f2h(float v) { return __half_as_ushort(__float2half_rn(v)); }
__device__ __forceinline__ uint32_t packh(float a, float b) {
    uint32_t r; asm("cvt.rn.f16x2.f32 %0, %1, %2;" : "=r"(r) : "f"(b), "f"(a)); return r;
}
__device__ __forceinline__ float2 up2(uint32_t u) { return __half22float2(*(__half2*)&u); }
__device__ __forceinline__ float h2f(const char* p) { return __half2float(*(const __half*)p); }

// ---------------- fused front-end ----------------
__global__ __launch_bounds__(512, 1)
void fused_tc_kernel(const float* __restrict__ x,
                     const float* __restrict__ W_in, const float* __restrict__ b_in,
                     const float* __restrict__ Wc,   const float* __restrict__ b_conv,
                     const float* __restrict__ Wq,   const float* __restrict__ bq,
                     const float* __restrict__ Wk,
                     const float* __restrict__ Wv,   const float* __restrict__ bv,
                     const float* __restrict__ W1,   const float* __restrict__ b1)
{
    extern __shared__ char smem[];
    const int tid = threadIdx.x, lane = tid & 31, wid = tid >> 5;
    const int g = lane >> 2, tig = lane & 3;

    // ---- W1' prep spread over grid ----
    {
        int idx = blockIdx.x * 512 + tid;
        if (idx < 16384) {
            int n = idx & 255, c = idx >> 8;
            float v = 0.f;
            #pragma unroll 8
            for (int j = 0; j < 64; j++)
                v += __ldg(&Wv[c*64 + j]) * __ldg(&W1[j*256 + n]);
            g_W1p[n*72 + c] = f2h(v);
            if (idx < 256) {
                float bb = b1[idx];
                #pragma unroll 8
                for (int j = 0; j < 64; j++)
                    bb += __ldg(&bv[j]) * __ldg(&W1[j*256 + idx]);
                g_b1p[idx] = bb;
            }
        }
    }

    float* beff = (float*)(smem+O_BEFF);
    float* c0r_ = (float*)(smem+O_C0R);
    float* c2r_ = (float*)(smem+O_C2R);

    // ---- one-time setup ----
    {
        float* WinS = (float*)(smem + O_XB);
        float* WcS  = (float*)(smem + O_XB + 8192);
        for (int i = tid; i < 2048; i += 512) WinS[i] = W_in[i];
        for (int kt = 0; kt < 3; kt++) {
            __syncthreads();
            for (int i = tid; i < 4096; i += 512) WcS[i] = Wc[kt*4096 + i];
            __syncthreads();
            for (int idx = tid; idx < 2048; idx += 512) {
                int c = idx & 63, e = idx >> 6;
                float v = 0.f;
                #pragma unroll 8
                for (int c0 = 0; c0 < 64; c0++)
                    v += WinS[e*64 + c0] * WcS[c0*64 + c];
                *(uint16_t*)(smem + O_WF + (c*PW + kt*32 + e)*2) = f2h(v);
            }
            if (tid < 64) {
                int c = tid; float s = 0.f;
                for (int c0 = 0; c0 < 64; c0++) s += b_in[c0] * WcS[c0*64 + c];
                if (kt == 0) { c0r_[c] = s; beff[c] = b_conv[c] + s; }
                else if (kt == 1) beff[c] += s;
                else { c2r_[c] = s; beff[c] += s; }
            }
        }
        __syncthreads();
        float* WqS = (float*)(smem + O_XB);
        float* WkS = (float*)(smem + O_XB + 16384);
        for (int i = tid; i < 4096; i += 512) { WqS[i] = Wq[i]; WkS[i] = Wk[i]; }
        __syncthreads();
        for (int idx = tid; idx < 4096; idx += 512) {
            int a = idx >> 6, c = idx & 63;
            float v = 0.f;
            #pragma unroll 8
            for (int d = 0; d < 64; d++) v += WqS[a*64 + d] * WkS[c*64 + d];
            *(uint16_t*)(smem + O_G + (a*64 + c)*2) = f2h(v);
        }
        if (tid < 64) {
            int c = tid; float s = 0.f;
            for (int d = 0; d < 64; d++) s += bq[d] * WkS[c*64 + d];
            ((float*)(smem+O_WB))[c] = s;
        }
        __syncthreads();
        for (int idx = tid; idx < 16*2*PX; idx += 512) {
            int w = idx / (2*PX), rr = (idx / PX) & 1, e = idx % PX;
            *(uint16_t*)(smem + O_XB + w*4096 + ((rr ? 49 : 0)*PX + e)*2) = 0;
        }
        __syncthreads();
    }

    char* Xw = smem + O_XB + wid*4096;
    char* Hw = smem + O_HC + wid*6400;
    float* wsp = (float*)(smem + O_WS + wid*512);
    float* esp = (float*)(smem + O_WS + wid*512 + 256);
    const float* wb = (const float*)(smem+O_WB);
    const int c0 = 2*lane;

    for (int s = blockIdx.x*16 + wid; s < SEQS; s += GRID_A*16) {
        const float4* xp4 = (const float4*)(x + (size_t)s * TT * 32);
        #pragma unroll
        for (int r = 0; r < 12; r++) {
            int j = r*32 + lane;
            float4 f4 = xp4[j];
            int t = j >> 3, e0 = (j & 7) * 4;
            uint2 u; u.x = packh(f4.x, f4.y); u.y = packh(f4.z, f4.w);
            *(uint2*)(Xw + ((t+1)*PX + e0)*2) = u;
        }
        __syncwarp();

        // conv GEMM, group A: f3 = 0,1 with B-fragment reuse
        {
            float acc[2][8][4];
            #pragma unroll
            for (int f = 0; f < 2; f++)
                #pragma unroll
                for (int nb = 0; nb < 8; nb++)
                    { acc[f][nb][0]=acc[f][nb][1]=acc[f][nb][2]=acc[f][nb][3]=0.f; }
            #pragma unroll
            for (int kt = 0; kt < 3; kt++) {
                #pragma unroll
                for (int ks = 0; ks < 2; ks++) {
                    int k0 = ks*16 + tig*2;
                    int xr0 = g + kt, xr1 = 16 + g + kt;
                    uint32_t p0 = *(const uint32_t*)(Xw + (xr0*PX      + k0)*2);
                    uint32_t p1 = *(const uint32_t*)(Xw + ((xr0+8)*PX  + k0)*2);
                    uint32_t p2 = *(const uint32_t*)(Xw + (xr0*PX      + k0+8)*2);
                    uint32_t p3 = *(const uint32_t*)(Xw + ((xr0+8)*PX  + k0+8)*2);
                    uint32_t q0 = *(const uint32_t*)(Xw + (xr1*PX      + k0)*2);
                    uint32_t q1 = *(const uint32_t*)(Xw + ((xr1+8)*PX  + k0)*2);
                    uint32_t q2 = *(const uint32_t*)(Xw + (xr1*PX      + k0+8)*2);
                    uint32_t q3 = *(const uint32_t*)(Xw + ((xr1+8)*PX  + k0+8)*2);
                    #pragma unroll
                    for (int nb = 0; nb < 8; nb++) {
                        uint32_t b0 = *(const uint32_t*)(smem + O_WF + ((nb*8+g)*PW + kt*32 + k0)*2);
                        uint32_t b1f = *(const uint32_t*)(smem + O_WF + ((nb*8+g)*PW + kt*32 + k0+8)*2);
                        MMA(acc[0][nb], p0, p1, p2, p3, b0, b1f);
                        MMA(acc[1][nb], q0, q1, q2, q3, b0, b1f);
                    }
                }
            }
            #pragma unroll
            for (int f = 0; f < 2; f++) {
                int t0 = f*16 + g, t1 = t0 + 8;
                bool e00 = (f == 0 && g == 0);
                #pragma unroll
                for (int nb = 0; nb < 8; nb++) {
                    int c = nb*8 + tig*2;
                    float ba0 = beff[c]   - (e00 ? c0r_[c]   : 0.f);
                    float bb0 = beff[c+1] - (e00 ? c0r_[c+1] : 0.f);
                    *(uint32_t*)(Hw + (t0*PHC + c)*2) =
                        packh(fmaxf(acc[f][nb][0]+ba0, 0.f), fmaxf(acc[f][nb][1]+bb0, 0.f));
                    *(uint32_t*)(Hw + (t1*PHC + c)*2) =
                        packh(fmaxf(acc[f][nb][2]+beff[c], 0.f), fmaxf(acc[f][nb][3]+beff[c+1], 0.f));
                }
            }
        }
        // group B: f3 = 2
        {
            float acc[8][4];
            #pragma unroll
            for (int nb = 0; nb < 8; nb++) { acc[nb][0]=acc[nb][1]=acc[nb][2]=acc[nb][3]=0.f; }
            #pragma unroll
            for (int kt = 0; kt < 3; kt++) {
                int xr = 32 + g + kt;
                #pragma unroll
                for (int ks = 0; ks < 2; ks++) {
                    int k0 = ks*16 + tig*2;
                    uint32_t a0 = *(const uint32_t*)(Xw + (xr*PX     + k0)*2);
                    uint32_t a1 = *(const uint32_t*)(Xw + ((xr+8)*PX + k0)*2);
                    uint32_t a2 = *(const uint32_t*)(Xw + (xr*PX     + k0+8)*2);
                    uint32_t a3 = *(const uint32_t*)(Xw + ((xr+8)*PX + k0+8)*2);
                    #pragma unroll
                    for (int nb = 0; nb < 8; nb++) {
                        uint32_t b0 = *(const uint32_t*)(smem + O_WF + ((nb*8+g)*PW + kt*32 + k0)*2);
                        uint32_t b1f = *(const uint32_t*)(smem + O_WF + ((nb*8+g)*PW + kt*32 + k0+8)*2);
                        MMA(acc[nb], a0, a1, a2, a3, b0, b1f);
                    }
                }
            }
            int t0 = 32 + g, t1 = t0 + 8;
            bool e147 = (g == 7);
            #pragma unroll
            for (int nb = 0; nb < 8; nb++) {
                int c = nb*8 + tig*2;
                float ba1 = beff[c]   - (e147 ? c2r_[c]   : 0.f);
                float bb1 = beff[c+1] - (e147 ? c2r_[c+1] : 0.f);
                *(uint32_t*)(Hw + (t0*PHC + c)*2) =
                    packh(fmaxf(acc[nb][0]+beff[c], 0.f), fmaxf(acc[nb][1]+beff[c+1], 0.f));
                *(uint32_t*)(Hw + (t1*PHC + c)*2) =
                    packh(fmaxf(acc[nb][2]+ba1, 0.f), fmaxf(acc[nb][3]+bb1, 0.f));
            }
        }
        __syncwarp();

        // prefetch next seq's x into L2
        {
            int ns = s + GRID_A*16;
            if (ns < SEQS) {
                const char* pn = (const char*)(x + (size_t)ns * 1536);
                asm volatile("prefetch.global.L2 [%0];" :: "l"(pn + (size_t)lane*128));
                if (lane < 16)
                    asm volatile("prefetch.global.L2 [%0];" :: "l"(pn + 4096 + (size_t)lane*128));
            }
        }

        // w[c] = wbias[c] + sum_a hc47[a] * G[a][c]  (packed loads, split chains)
        {
            float w0a = 0.f, w0b = 0.f, w1a = 0.f, w1b = 0.f;
            #pragma unroll 8
            for (int a = 0; a < 64; a += 2) {
                float2 hp = up2(*(const uint32_t*)(Hw + (47*PHC + a)*2));
                float2 g0 = up2(*(const uint32_t*)(smem + O_G + (a*64 + c0)*2));
                float2 g1 = up2(*(const uint32_t*)(smem + O_G + ((a+1)*64 + c0)*2));
                w0a += hp.x * g0.x; w1a += hp.x * g0.y;
                w0b += hp.y * g1.x; w1b += hp.y * g1.y;
            }
            wsp[c0]   = wb[c0]   + w0a + w0b;
            wsp[c0+1] = wb[c0+1] + w1a + w1b;
        }
        __syncwarp();

        // scores + softmax (split accumulator chains)
        float S;
        {
            float s0a = 0.f, s0b = 0.f, s1a = 0.f, s1b = 0.f;
            #pragma unroll 8
            for (int cc = 0; cc < 64; cc += 4) {
                float2 wv0 = *(const float2*)(wsp + cc);
                float2 wv1 = *(const float2*)(wsp + cc + 2);
                float2 ha0 = up2(*(const uint32_t*)(Hw + (lane*PHC + cc)*2));
                float2 ha1 = up2(*(const uint32_t*)(Hw + (lane*PHC + cc+2)*2));
                s0a += ha0.x * wv0.x + ha0.y * wv0.y;
                s0b += ha1.x * wv1.x + ha1.y * wv1.y;
                if (lane < 16) {
                    float2 hb0 = up2(*(const uint32_t*)(Hw + ((lane+32)*PHC + cc)*2));
                    float2 hb1 = up2(*(const uint32_t*)(Hw + ((lane+32)*PHC + cc+2)*2));
                    s1a += hb0.x * wv0.x + hb0.y * wv0.y;
                    s1b += hb1.x * wv1.x + hb1.y * wv1.y;
                }
            }
            float s0 = (s0a + s0b) * 0.125f;
            float s1 = (s1a + s1b) * 0.125f;
            float m = (lane < 16) ? fmaxf(s0, s1) : s0;
            #pragma unroll
            for (int o = 16; o > 0; o >>= 1) m = fmaxf(m, __shfl_xor_sync(0xffffffffu, m, o));
            float e0 = __expf(s0 - m);
            float e1 = (lane < 16) ? __expf(s1 - m) : 0.f;
            float loc = e0 + e1;
            #pragma unroll
            for (int o = 16; o > 0; o >>= 1) loc += __shfl_xor_sync(0xffffffffu, loc, o);
            S = loc;
            esp[lane] = e0;
            if (lane < 16) esp[lane + 32] = e1;
        }
        __syncwarp();

        // g_last = (sum_t e_t * hc_t) / S  (float4 esp reads, split chains)
        {
            float a0a = 0.f, a0b = 0.f, a1a = 0.f, a1b = 0.f;
            #pragma unroll
            for (int t = 0; t < TT; t += 4) {
                float4 e4 = *(const float4*)(esp + t);
                float2 h0 = up2(*(const uint32_t*)(Hw + ((t+0)*PHC + c0)*2));
                float2 h1 = up2(*(const uint32_t*)(Hw + ((t+1)*PHC + c0)*2));
                float2 h2v = up2(*(const uint32_t*)(Hw + ((t+2)*PHC + c0)*2));
                float2 h3 = up2(*(const uint32_t*)(Hw + ((t+3)*PHC + c0)*2));
                a0a += e4.x * h0.x + e4.y * h1.x;
                a1a += e4.x * h0.y + e4.y * h1.y;
                a0b += e4.z * h2v.x + e4.w * h3.x;
                a1b += e4.z * h2v.y + e4.w * h3.y;
            }
            float inv = __fdividef(1.0f, S);
            float2 res; res.x = (a0a + a0b) * inv; res.y = (a1a + a1b) * inv;
            *(float2*)(&g_last[(size_t)s*CC + c0]) = res;
        }
    }
}

// ---------------- MLP: persistent 148 CTAs, 512 threads (unchanged, verified) ----------------
__global__ __launch_bounds__(512, 1)
void mlp_kernel(const float* __restrict__ W2, const float* __restrict__ b2,
                const float* __restrict__ W3, const float* __restrict__ b3,
                float* __restrict__ out)
{
    extern __shared__ char smem[];
    const int tid = threadIdx.x, lane = tid & 31, wid = tid >> 5;
    const int g = lane >> 2, tig = lane & 3;
    const int wm = wid & 7, wn = wid >> 3;
    const int r0 = wm * 16;

    for (int idx = tid; idx < 128*128; idx += 512) {
        int n = idx & 127, k0 = (idx >> 7) * 2;
        *(uint32_t*)(smem + M_W2 + (n*264 + k0)*2) = packh(W2[k0*H2 + n], W2[(k0+1)*H2 + n]);
    }
    for (int idx = tid; idx < 16*64; idx += 512) {
        int n = idx & 15, k0 = (idx >> 4) * 2;
        float v0 = (n < NPRED) ? W3[k0*NPRED + n] : 0.f;
        float v1 = (n < NPRED) ? W3[(k0+1)*NPRED + n] : 0.f;
        *(uint32_t*)(smem + M_W3 + (n*136 + k0)*2) = packh(v0, v1);
    }

    for (int tile = blockIdx.x; tile < NTILE_B; tile += GRID_B) {
        const int row0 = tile * 128;
        __syncthreads();

        for (int i = tid; i < 9216; i += 512)
            ((uint32_t*)(smem + M_W1))[i] = ((const uint32_t*)g_W1p)[i];
        for (int idx = tid; idx < 128*32; idx += 512) {
            int r = idx >> 5, c0 = (idx & 31) * 2;
            const float* lp = &g_last[(size_t)(row0 + r)*CC + c0];
            *(uint32_t*)(smem + M_LAST + (r*72 + c0)*2) = packh(lp[0], lp[1]);
        }
        __syncthreads();

        // layer 1
        #pragma unroll
        for (int c2 = 0; c2 < 2; c2++) {
            float acc[8][4];
            #pragma unroll
            for (int nb = 0; nb < 8; nb++) { acc[nb][0]=acc[nb][1]=acc[nb][2]=acc[nb][3]=0.f; }
            #pragma unroll
            for (int ks = 0; ks < 4; ks++) {
                int k0 = ks*16 + tig*2;
                uint32_t a0 = *(const uint32_t*)(smem + M_LAST + ((r0+g)*72   + k0)*2);
                uint32_t a1 = *(const uint32_t*)(smem + M_LAST + ((r0+g+8)*72 + k0)*2);
                uint32_t a2 = *(const uint32_t*)(smem + M_LAST + ((r0+g)*72   + k0+8)*2);
                uint32_t a3 = *(const uint32_t*)(smem + M_LAST + ((r0+g+8)*72 + k0+8)*2);
                #pragma unroll
                for (int nb = 0; nb < 8; nb++) {
                    int n = wn*128 + c2*64 + nb*8 + g;
                    uint32_t b0 = *(const uint32_t*)(smem + M_W1 + (n*72 + k0)*2);
                    uint32_t b1r = *(const uint32_t*)(smem + M_W1 + (n*72 + k0+8)*2);
                    MMA(acc[nb], a0, a1, a2, a3, b0, b1r);
                }
            }
            int m0 = r0 + g, m1 = m0 + 8;
            #pragma unroll
            for (int nb = 0; nb < 8; nb++) {
                int h = wn*128 + c2*64 + nb*8 + tig*2;
                float bb0 = g_b1p[h], bb1 = g_b1p[h+1];
                *(uint32_t*)(smem + M_Z1 + (m0*264 + h)*2) =
                    packh(fmaxf(acc[nb][0]+bb0, 0.f), fmaxf(acc[nb][1]+bb1, 0.f));
                *(uint32_t*)(smem + M_Z1 + (m1*264 + h)*2) =
                    packh(fmaxf(acc[nb][2]+bb0, 0.f), fmaxf(acc[nb][3]+bb1, 0.f));
            }
        }
        __syncthreads();

        // layer 2
        {
            float acc[8][4];
            #pragma unroll
            for (int nb = 0; nb < 8; nb++) { acc[nb][0]=acc[nb][1]=acc[nb][2]=acc[nb][3]=0.f; }
            #pragma unroll
            for (int ks = 0; ks < 16; ks++) {
                int k0 = ks*16 + tig*2;
                uint32_t a0 = *(const uint32_t*)(smem + M_Z1 + ((r0+g)*264   + k0)*2);
                uint32_t a1 = *(const uint32_t*)(smem + M_Z1 + ((r0+g+8)*264 + k0)*2);
                uint32_t a2 = *(const uint32_t*)(smem + M_Z1 + ((r0+g)*264   + k0+8)*2);
                uint32_t a3 = *(const uint32_t*)(smem + M_Z1 + ((r0+g+8)*264 + k0+8)*2);
                #pragma unroll
                for (int nb = 0; nb < 8; nb++) {
                    int n = wn*64 + nb*8 + g;
                    uint32_t b0 = *(const uint32_t*)(smem + M_W2 + (n*264 + k0)*2);
                    uint32_t b1r = *(const uint32_t*)(smem + M_W2 + (n*264 + k0+8)*2);
                    MMA(acc[nb], a0, a1, a2, a3, b0, b1r);
                }
            }
            int m0 = r0 + g, m1 = m0 + 8;
            #pragma unroll
            for (int nb = 0; nb < 8; nb++) {
                int h = wn*64 + nb*8 + tig*2;
                float bb0 = __ldg(&b2[h]), bb1 = __ldg(&b2[h+1]);
                *(uint32_t*)(smem + M_Z2 + (m0*136 + h)*2) =
                    packh(fmaxf(acc[nb][0]+bb0, 0.f), fmaxf(acc[nb][1]+bb1, 0.f));
                *(uint32_t*)(smem + M_Z2 + (m1*136 + h)*2) =
                    packh(fmaxf(acc[nb][2]+bb0, 0.f), fmaxf(acc[nb][3]+bb1, 0.f));
            }
        }
        __syncthreads();

        // layer 3
        {
            float acc[4] = {0.f, 0.f, 0.f, 0.f};
            #pragma unroll
            for (int ks = 0; ks < 8; ks++) {
                int k0 = ks*16 + tig*2;
                uint32_t a0 = *(const uint32_t*)(smem + M_Z2 + ((r0+g)*136   + k0)*2);
                uint32_t a1 = *(const uint32_t*)(smem + M_Z2 + ((r0+g+8)*136 + k0)*2);
                uint32_t a2 = *(const uint32_t*)(smem + M_Z2 + ((r0+g)*136   + k0+8)*2);
                uint32_t a3 = *(const uint32_t*)(smem + M_Z2 + ((r0+g+8)*136 + k0+8)*2);
                int n = wn*8 + g;
                uint32_t b0 = *(const uint32_t*)(smem + M_W3 + (n*136 + k0)*2);
                uint32_t b1r = *(const uint32_t*)(smem + M_W3 + (n*136 + k0+8)*2);
                MMA(acc, a0, a1, a2, a3, b0, b1r);
            }
            int m0 = r0 + g, m1 = m0 + 8;
            int g0 = row0 + m0, g1 = row0 + m1;
            int b0i = g0 >> 11, n0i = g0 & 2047;
            int b1i = g1 >> 11, n1i = g1 & 2047;
            int p = wn*8 + tig*2;
            if (p < NPRED) {
                float bp = __ldg(&b3[p]);
                out[((size_t)b0i*NPRED + p)*2048 + n0i] = acc[0] + bp;
                out[((size_t)b1i*NPRED + p)*2048 + n1i] = acc[2] + bp;
            }
            if (p + 1 < NPRED) {
                float bp = __ldg(&b3[p+1]);
                out[((size_t)b0i*NPRED + p+1)*2048 + n0i] = acc[1] + bp;
                out[((size_t)b1i*NPRED + p+1)*2048 + n1i] = acc[3] + bp;
            }
        }
    }
}

extern "C" void kernel_launch(void* const* d_in, const int* in_sizes, int n_in,
                              void* d_out, int out_size)
{
    (void)in_sizes; (void)n_in; (void)out_size;
    const float* x      = (const float*)d_in[0];
    const float* W_in   = (const float*)d_in[1];
    const float* b_in   = (const float*)d_in[2];
    const float* W_conv = (const float*)d_in[3];
    const float* b_conv = (const float*)d_in[4];
    const float* Wq     = (const float*)d_in[5];
    const float* bq     = (const float*)d_in[6];
    const float* Wk     = (const float*)d_in[7];
    const float* Wv     = (const float*)d_in[9];
    const float* bv     = (const float*)d_in[10];
    const float* W1     = (const float*)d_in[11];
    const float* b1     = (const float*)d_in[12];
    const float* W2     = (const float*)d_in[13];
    const float* b2     = (const float*)d_in[14];
    const float* W3     = (const float*)d_in[15];
    const float* b3     = (const float*)d_in[16];
    float* out = (float*)d_out;

    cudaFuncSetAttribute(fused_tc_kernel, cudaFuncAttributeMaxDynamicSharedMemorySize, SMEMA);
    cudaFuncSetAttribute(mlp_kernel, cudaFuncAttributeMaxDynamicSharedMemorySize, SMEMB);

    fused_tc_kernel<<<GRID_A, 512, SMEMA>>>(
        x, W_in, b_in, W_conv, b_conv, Wq, bq, Wk, Wv, bv, W1, b1);
    mlp_kernel<<<GRID_B, 512, SMEMB>>>(W2, b2, W3, b3, out);
}